// round 13
// baseline (speedup 1.0000x reference)
#include <cuda_runtime.h>
#include <math.h>
#include <stdint.h>

// Problem constants
#define BB 512
#define NN 64
#define EE 512
#define AA 16
#define ITERS 8
#define TPB 512          // threads per CTA (one CTA per batch)
#define EINV (1.0f / 512.0f)

// Adjacency (CSR, ascending edge order) -- built once per launch on device.
__device__ int g_to_off[NN + 1], g_from_off[NN + 1];
__device__ int g_to_lst[EE], g_from_lst[EE];

__global__ void build_adj_kernel(const int* __restrict__ ef, const int* __restrict__ et) {
    __shared__ int sf[EE], st[EE];
    __shared__ int cto[NN], cfr[NN];
    int t = threadIdx.x;
    for (int e = t; e < EE; e += blockDim.x) { sf[e] = ef[e]; st[e] = et[e]; }
    __syncthreads();
    if (t < NN) {
        int ct = 0, cf = 0;
        for (int e = 0; e < EE; e++) { ct += (st[e] == t); cf += (sf[e] == t); }
        cto[t] = ct; cfr[t] = cf;
    }
    __syncthreads();
    if (t == 0) {
        int a = 0, b = 0;
        for (int n = 0; n < NN; n++) {
            g_to_off[n] = a; a += cto[n];
            g_from_off[n] = b; b += cfr[n];
        }
        g_to_off[NN] = a; g_from_off[NN] = b;
    }
    __syncthreads();
    if (t < NN) {
        int ot = g_to_off[t], of = g_from_off[t];
        for (int e = 0; e < EE; e++) {
            if (st[e] == t) g_to_lst[ot++] = e;
            if (sf[e] == t) g_from_lst[of++] = e;
        }
    }
}

// SMEM layout (floats):
//  q0:1024  q:1024  mf:8192  mb:8192
//  red:16 red_node:2 qmax:1  ints: a_cur:64 a_best:64 flag:1 ef:512 et:512
#define SMEM_WORDS (1024 + 1024 + 8192 + 8192 + 16 + 2 + 1 + 64 + 64 + 1 + 512 + 512)
// pad to 120KB: forces occupancy 1 so the 148 resident CTAs' edge tiles
// (148 x 512KB = 76MB) fit in the 126MB L2 -> iteration re-reads are L2 hits.
#define SMEM_BYTES (120 * 1024)

__device__ __forceinline__ float4 f4_sub(float4 a, float4 b) {
    float4 r;
    r.x = a.x - b.x; r.y = a.y - b.y; r.z = a.z - b.z; r.w = a.w - b.w;
    return r;
}
// max over 4 elements of (T*EINV + u[j])  -- exact: T*EINV product exact,
// single rounding per add, fmax exactly associative.
__device__ __forceinline__ float seg_max(float4 T, float4 u) {
    float a = fmaxf(fmaf(T.x, EINV, u.x), fmaf(T.y, EINV, u.y));
    float b = fmaxf(fmaf(T.z, EINV, u.z), fmaf(T.w, EINV, u.w));
    return fmaxf(a, b);
}

__global__ __launch_bounds__(TPB, 1)
void dcg_kernel(const float* __restrict__ nodev, const float* __restrict__ edgev,
                const int* __restrict__ ef, const int* __restrict__ et,
                float* __restrict__ out)
{
    extern __shared__ float smem[];
    float* q0      = smem;                        // 1024
    float* q       = q0 + 1024;                   // 1024
    float* mf      = q + 1024;                    // 8192
    float* mb      = mf + 8192;                   // 8192
    float* red     = mb + 8192;                   // 16
    float* red_node = red + 16;                   // 2
    float* qmax_s  = red_node + 2;                // 1
    int* a_cur  = (int*)(qmax_s + 1);             // 64
    int* a_best = a_cur + 64;                     // 64
    int* flag   = a_best + 64;                    // 1
    int* ef_s   = flag + 1;                       // 512
    int* et_s   = ef_s + EE;                      // 512

    const int tid    = threadIdx.x;
    const int b      = blockIdx.x;
    const int halfid = tid >> 4;        // 0..31 half-warp id
    const int hl     = tid & 15;        // lane within half-warp
    const int sseg   = hl & 3;          // column segment s (cols 4s..4s+3)
    const int kgrp   = hl >> 2;         // row-group k (rows 4i+k)
    const unsigned hmask = 0xFFFFu << ((halfid & 1) * 16);
    const int warp = tid >> 5;
    const int lane = tid & 31;
    // reduce-scatter final index permutation: perm[x] = [0,2,1,3][x]
    const int permS = ((sseg & 1) << 1) | (sseg >> 1);
    const int permK = ((kgrp & 1) << 1) | (kgrp >> 1);

    const float* nb    = nodev + (size_t)b * NN * AA;
    const float* ebase = edgev + (size_t)b * EE * AA * AA;

    // ---- init
    for (int i = tid; i < NN * AA; i += TPB) {
        float v = nb[i] * 0.015625f;   // /64 exact
        q0[i] = v; q[i] = v;
    }
    for (int i = tid; i < EE * AA; i += TPB) { mf[i] = 0.f; mb[i] = 0.f; }
    for (int i = tid; i < EE; i += TPB) { ef_s[i] = ef[i]; et_s[i] = et[i]; }
    __syncthreads();

    // ---- argmax of q-array per node (lowest index wins ties, like jnp.argmax)
    auto do_argmax = [&](const float* qa) {
        for (int n = halfid; n < NN; n += 32) {
            float bv = qa[n * AA + hl]; int bi = hl;
            #pragma unroll
            for (int o = 8; o; o >>= 1) {
                float ov = __shfl_xor_sync(hmask, bv, o, 16);
                int   oi = __shfl_xor_sync(hmask, bi, o, 16);
                if (ov > bv || (ov == bv && oi < bi)) { bv = ov; bi = oi; }
            }
            if (hl == 0) a_cur[n] = bi;
        }
    };

    // ---- evaluate action a_cur, update (q_max, a_best). Caller syncs before.
    auto do_eval = [&](bool first) {
        float ev;
        {
            int e  = tid;
            int af = a_cur[ef_s[e]];
            int at = a_cur[et_s[e]];
            ev = ebase[(size_t)e * 256 + af * 16 + at];
        }
        #pragma unroll
        for (int o = 16; o; o >>= 1) ev += __shfl_xor_sync(0xffffffffu, ev, o, 32);
        if (lane == 0) red[warp] = ev;
        if (tid < NN) {
            float nv = q0[tid * AA + a_cur[tid]] * 64.0f;   // node_vals exact
            #pragma unroll
            for (int o = 16; o; o >>= 1) nv += __shfl_xor_sync(0xffffffffu, nv, o, 32);
            if (lane == 0) red_node[warp] = nv;
        }
        __syncthreads();
        if (tid == 0) {
            float es = 0.f;
            #pragma unroll
            for (int w = 0; w < 16; w++) es += red[w];
            float ns = red_node[0] + red_node[1];
            float qv = ns * (1.0f / 64.0f) + es * (1.0f / 512.0f);
            if (first || qv > *qmax_s) { *qmax_s = qv; *flag = 1; }
            else *flag = 0;
        }
        __syncthreads();
        if (*flag && tid < NN) a_best[tid] = a_cur[tid];
        __syncthreads();
    };

    // ---- initial: a_max = argmax(node_vals), q_max = eval
    do_argmax(q0);
    __syncthreads();
    do_eval(true);

    // ---- message-passing iterations
    for (int it = 0; it < ITERS; it++) {
        // Phase 1: TWO edges per half-warp per pair-pass (independent
        // pipelines for latency hiding; occ-1 frees the register budget).
        // Per-edge computation is instruction-for-instruction the proven R12
        // sequence: coalesced chunk-ownership loads, exact fmax reduce-
        // scatters, mean butterflies matching the pinned association tree.
        for (int pp = 0; pp < 8; ++pp) {
            const int eA = halfid + 64 * pp;
            const int eB = eA + 32;
            const int nfA = ef_s[eA], ntA = et_s[eA];
            const int nfB = ef_s[eB], ntB = et_s[eB];

            // ---- hoisted old-state loads (both edges, before any store)
            const float4 ubvA = f4_sub(*(const float4*)(q  + ntA * AA + 4 * sseg),
                                       *(const float4*)(mf + eA  * AA + 4 * sseg));
            const float4 ubvB = f4_sub(*(const float4*)(q  + ntB * AA + 4 * sseg),
                                       *(const float4*)(mf + eB  * AA + 4 * sseg));
            const float ufA0 = q[nfA * AA + 0  + kgrp] - mb[eA * AA + 0  + kgrp];
            const float ufA1 = q[nfA * AA + 4  + kgrp] - mb[eA * AA + 4  + kgrp];
            const float ufA2 = q[nfA * AA + 8  + kgrp] - mb[eA * AA + 8  + kgrp];
            const float ufA3 = q[nfA * AA + 12 + kgrp] - mb[eA * AA + 12 + kgrp];
            const float ufB0 = q[nfB * AA + 0  + kgrp] - mb[eB * AA + 0  + kgrp];
            const float ufB1 = q[nfB * AA + 4  + kgrp] - mb[eB * AA + 4  + kgrp];
            const float ufB2 = q[nfB * AA + 8  + kgrp] - mb[eB * AA + 8  + kgrp];
            const float ufB3 = q[nfB * AA + 12 + kgrp] - mb[eB * AA + 12 + kgrp];

            // ---- coalesced tile loads (both edges -> 8 independent LDG.128)
            const float4* gA = (const float4*)(ebase + (size_t)eA * 256);
            const float4* gB = (const float4*)(ebase + (size_t)eB * 256);
            const float4 TA0 = gA[ 0 + hl], TA1 = gA[16 + hl];
            const float4 TA2 = gA[32 + hl], TA3 = gA[48 + hl];
            const float4 TB0 = gB[ 0 + hl], TB1 = gB[16 + hl];
            const float4 TB2 = gB[32 + hl], TB3 = gB[48 + hl];

            // ---- mb partials
            float pA0 = seg_max(TA0, ubvA), pA1 = seg_max(TA1, ubvA);
            float pA2 = seg_max(TA2, ubvA), pA3 = seg_max(TA3, ubvA);
            float pB0 = seg_max(TB0, ubvB), pB1 = seg_max(TB1, ubvB);
            float pB2 = seg_max(TB2, ubvB), pB3 = seg_max(TB3, ubvB);
            // reduce-scatter over s (xor 1 then 2), both edges interleaved
            float mbvA, mbvB;
            {
                const bool s0 = (sseg & 1) != 0;
                float sd0A = s0 ? pA0 : pA2, sd1A = s0 ? pA1 : pA3;
                float kp0A = s0 ? pA2 : pA0, kp1A = s0 ? pA3 : pA1;
                float sd0B = s0 ? pB0 : pB2, sd1B = s0 ? pB1 : pB3;
                float kp0B = s0 ? pB2 : pB0, kp1B = s0 ? pB3 : pB1;
                float r0A = __shfl_xor_sync(hmask, sd0A, 1, 16);
                float r1A = __shfl_xor_sync(hmask, sd1A, 1, 16);
                float r0B = __shfl_xor_sync(hmask, sd0B, 1, 16);
                float r1B = __shfl_xor_sync(hmask, sd1B, 1, 16);
                float a0A = fmaxf(kp0A, r0A), a1A = fmaxf(kp1A, r1A);
                float a0B = fmaxf(kp0B, r0B), a1B = fmaxf(kp1B, r1B);
                const bool s1 = (sseg & 2) != 0;
                float sdA = s1 ? a0A : a1A, kpA = s1 ? a1A : a0A;
                float sdB = s1 ? a0B : a1B, kpB = s1 ? a1B : a0B;
                float rA = __shfl_xor_sync(hmask, sdA, 2, 16);
                float rB = __shfl_xor_sync(hmask, sdB, 2, 16);
                mbvA = fmaxf(kpA, rA);
                mbvB = fmaxf(kpB, rB);
            }

            // ---- mf candidates (per owned column), both edges
            float cxA = fmaxf(fmaxf(fmaf(TA0.x, EINV, ufA0), fmaf(TA1.x, EINV, ufA1)),
                              fmaxf(fmaf(TA2.x, EINV, ufA2), fmaf(TA3.x, EINV, ufA3)));
            float cyA = fmaxf(fmaxf(fmaf(TA0.y, EINV, ufA0), fmaf(TA1.y, EINV, ufA1)),
                              fmaxf(fmaf(TA2.y, EINV, ufA2), fmaf(TA3.y, EINV, ufA3)));
            float czA = fmaxf(fmaxf(fmaf(TA0.z, EINV, ufA0), fmaf(TA1.z, EINV, ufA1)),
                              fmaxf(fmaf(TA2.z, EINV, ufA2), fmaf(TA3.z, EINV, ufA3)));
            float cwA = fmaxf(fmaxf(fmaf(TA0.w, EINV, ufA0), fmaf(TA1.w, EINV, ufA1)),
                              fmaxf(fmaf(TA2.w, EINV, ufA2), fmaf(TA3.w, EINV, ufA3)));
            float cxB = fmaxf(fmaxf(fmaf(TB0.x, EINV, ufB0), fmaf(TB1.x, EINV, ufB1)),
                              fmaxf(fmaf(TB2.x, EINV, ufB2), fmaf(TB3.x, EINV, ufB3)));
            float cyB = fmaxf(fmaxf(fmaf(TB0.y, EINV, ufB0), fmaf(TB1.y, EINV, ufB1)),
                              fmaxf(fmaf(TB2.y, EINV, ufB2), fmaf(TB3.y, EINV, ufB3)));
            float czB = fmaxf(fmaxf(fmaf(TB0.z, EINV, ufB0), fmaf(TB1.z, EINV, ufB1)),
                              fmaxf(fmaf(TB2.z, EINV, ufB2), fmaf(TB3.z, EINV, ufB3)));
            float cwB = fmaxf(fmaxf(fmaf(TB0.w, EINV, ufB0), fmaf(TB1.w, EINV, ufB1)),
                              fmaxf(fmaf(TB2.w, EINV, ufB2), fmaf(TB3.w, EINV, ufB3)));
            // reduce-scatter over k (xor 4 then 8), both edges interleaved
            float mfvA, mfvB;
            {
                const bool k0 = (kgrp & 1) != 0;
                float sd0A = k0 ? cxA : czA, sd1A = k0 ? cyA : cwA;
                float kp0A = k0 ? czA : cxA, kp1A = k0 ? cwA : cyA;
                float sd0B = k0 ? cxB : czB, sd1B = k0 ? cyB : cwB;
                float kp0B = k0 ? czB : cxB, kp1B = k0 ? cwB : cyB;
                float r0A = __shfl_xor_sync(hmask, sd0A, 4, 16);
                float r1A = __shfl_xor_sync(hmask, sd1A, 4, 16);
                float r0B = __shfl_xor_sync(hmask, sd0B, 4, 16);
                float r1B = __shfl_xor_sync(hmask, sd1B, 4, 16);
                float a0A = fmaxf(kp0A, r0A), a1A = fmaxf(kp1A, r1A);
                float a0B = fmaxf(kp0B, r0B), a1B = fmaxf(kp1B, r1B);
                const bool k1 = (kgrp & 2) != 0;
                float sdA = k1 ? a0A : a1A, kpA = k1 ? a1A : a0A;
                float sdB = k1 ? a0B : a1B, kpB = k1 ? a1B : a0B;
                float rA = __shfl_xor_sync(hmask, sdA, 8, 16);
                float rB = __shfl_xor_sync(hmask, sdB, 8, 16);
                mfvA = fmaxf(kpA, rA);
                mfvB = fmaxf(kpB, rB);
            }

            // ---- means (pinned association trees; 4 interleaved butterflies)
            float smbA = mbvA, smbB = mbvB;
            smbA += __shfl_xor_sync(hmask, smbA, 1, 16);
            smbB += __shfl_xor_sync(hmask, smbB, 1, 16);
            smbA += __shfl_xor_sync(hmask, smbA, 2, 16);
            smbB += __shfl_xor_sync(hmask, smbB, 2, 16);
            smbA += __shfl_xor_sync(hmask, smbA, 8, 16);
            smbB += __shfl_xor_sync(hmask, smbB, 8, 16);
            smbA += __shfl_xor_sync(hmask, smbA, 4, 16);
            smbB += __shfl_xor_sync(hmask, smbB, 4, 16);
            float smfA = mfvA, smfB = mfvB;
            smfA += __shfl_xor_sync(hmask, smfA, 2, 16);
            smfB += __shfl_xor_sync(hmask, smfB, 2, 16);
            smfA += __shfl_xor_sync(hmask, smfA, 1, 16);
            smfB += __shfl_xor_sync(hmask, smfB, 1, 16);
            smfA += __shfl_xor_sync(hmask, smfA, 4, 16);
            smfB += __shfl_xor_sync(hmask, smfB, 4, 16);
            smfA += __shfl_xor_sync(hmask, smfA, 8, 16);
            smfB += __shfl_xor_sync(hmask, smfB, 8, 16);

            // ---- stores (bijective; shuffles ordered all old-state loads
            // of BOTH edges before these writes; eA != eB so disjoint)
            mb[eA * AA + 4 * permS + kgrp] = mbvA - smbA * 0.0625f;
            mb[eB * AA + 4 * permS + kgrp] = mbvB - smbB * 0.0625f;
            mf[eA * AA + 4 * sseg + permK] = mfvA - smfA * 0.0625f;
            mf[eB * AA + 4 * sseg + permK] = mfvB - smfB * 0.0625f;
        }
        __syncthreads();

        // Phase 2: q = q0 + scatter(mf over edges_to) + scatter(mb over edges_from)
        // per node in ascending-edge order, then per-node argmax.
        for (int n = halfid; n < NN; n += 32) {
            float acc = q0[n * AA + hl];
            int o0 = g_to_off[n], o1 = g_to_off[n + 1];
            for (int i = o0; i < o1; i++) acc += mf[g_to_lst[i] * AA + hl];
            o0 = g_from_off[n]; o1 = g_from_off[n + 1];
            for (int i = o0; i < o1; i++) acc += mb[g_from_lst[i] * AA + hl];
            q[n * AA + hl] = acc;
            float bv = acc; int bi = hl;
            #pragma unroll
            for (int o = 8; o; o >>= 1) {
                float ov = __shfl_xor_sync(hmask, bv, o, 16);
                int   oi = __shfl_xor_sync(hmask, bi, o, 16);
                if (ov > bv || (ov == bv && oi < bi)) { bv = ov; bi = oi; }
            }
            if (hl == 0) a_cur[n] = bi;
        }
        __syncthreads();

        // Phase 3: evaluate greedy action, keep best
        do_eval(false);
    }

    // ---- output: concat(q_max[B], float(a_max[B,N]))
    if (tid == 0) out[b] = *qmax_s;
    if (tid < NN) out[BB + (size_t)b * NN + tid] = (float)a_best[tid];
}

extern "C" void kernel_launch(void* const* d_in, const int* in_sizes, int n_in,
                              void* d_out, int out_size)
{
    const float* nodev = (const float*)d_in[0];   // (B,N,A) f32
    const float* edgev = (const float*)d_in[1];   // (B,E,A,A) f32
    const int*   ef    = (const int*)d_in[2];     // (E,) i32
    const int*   et    = (const int*)d_in[3];     // (E,) i32
    float* out = (float*)d_out;

    static bool attr_set = false;
    if (!attr_set) {
        cudaFuncSetAttribute(dcg_kernel, cudaFuncAttributeMaxDynamicSharedMemorySize, SMEM_BYTES);
        attr_set = true;
    }

    build_adj_kernel<<<1, 64>>>(ef, et);
    dcg_kernel<<<BB, TPB, SMEM_BYTES>>>(nodev, edgev, ef, et, out);
}

// round 14
// speedup vs baseline: 1.1210x; 1.1210x over previous
#include <cuda_runtime.h>
#include <math.h>
#include <stdint.h>

// Problem constants
#define BB 512
#define NN 64
#define EE 512
#define AA 16
#define ITERS 8
#define TPB 1024         // threads per CTA (one CTA per batch; fat CTA, occ 1)
#define NHW (TPB / 16)   // 64 half-warps
#define EINV (1.0f / 512.0f)

// Adjacency (CSR, ascending edge order) -- built once per launch on device.
__device__ int g_to_off[NN + 1], g_from_off[NN + 1];
__device__ int g_to_lst[EE], g_from_lst[EE];

__global__ void build_adj_kernel(const int* __restrict__ ef, const int* __restrict__ et) {
    __shared__ int sf[EE], st[EE];
    __shared__ int cto[NN], cfr[NN];
    int t = threadIdx.x;
    for (int e = t; e < EE; e += blockDim.x) { sf[e] = ef[e]; st[e] = et[e]; }
    __syncthreads();
    if (t < NN) {
        int ct = 0, cf = 0;
        for (int e = 0; e < EE; e++) { ct += (st[e] == t); cf += (sf[e] == t); }
        cto[t] = ct; cfr[t] = cf;
    }
    __syncthreads();
    if (t == 0) {
        int a = 0, b = 0;
        for (int n = 0; n < NN; n++) {
            g_to_off[n] = a; a += cto[n];
            g_from_off[n] = b; b += cfr[n];
        }
        g_to_off[NN] = a; g_from_off[NN] = b;
    }
    __syncthreads();
    if (t < NN) {
        int ot = g_to_off[t], of = g_from_off[t];
        for (int e = 0; e < EE; e++) {
            if (st[e] == t) g_to_lst[ot++] = e;
            if (sf[e] == t) g_from_lst[of++] = e;
        }
    }
}

// SMEM layout (floats):
//  q0:1024  q:1024  mf:8192  mb:8192
//  red:16 red_node:2 qmax:1  ints: a_cur:64 a_best:64 flag:1 ef:512 et:512
#define SMEM_WORDS (1024 + 1024 + 8192 + 8192 + 16 + 2 + 1 + 64 + 64 + 1 + 512 + 512)
// pad to 120KB: guarantees 1 CTA/SM (with the 64-reg cap) so the 148 resident
// CTAs' edge tiles (148 x 512KB = 76MB) stay L2-resident across iterations.
#define SMEM_BYTES (120 * 1024)

__device__ __forceinline__ float4 f4_sub(float4 a, float4 b) {
    float4 r;
    r.x = a.x - b.x; r.y = a.y - b.y; r.z = a.z - b.z; r.w = a.w - b.w;
    return r;
}
// max over 4 elements of (T*EINV + u[j])  -- exact: T*EINV product exact,
// single rounding per add, fmax exactly associative.
__device__ __forceinline__ float seg_max(float4 T, float4 u) {
    float a = fmaxf(fmaf(T.x, EINV, u.x), fmaf(T.y, EINV, u.y));
    float b = fmaxf(fmaf(T.z, EINV, u.z), fmaf(T.w, EINV, u.w));
    return fmaxf(a, b);
}

__global__ __launch_bounds__(TPB, 1)
void dcg_kernel(const float* __restrict__ nodev, const float* __restrict__ edgev,
                const int* __restrict__ ef, const int* __restrict__ et,
                float* __restrict__ out)
{
    extern __shared__ float smem[];
    float* q0      = smem;                        // 1024
    float* q       = q0 + 1024;                   // 1024
    float* mf      = q + 1024;                    // 8192
    float* mb      = mf + 8192;                   // 8192
    float* red     = mb + 8192;                   // 16
    float* red_node = red + 16;                   // 2
    float* qmax_s  = red_node + 2;                // 1
    int* a_cur  = (int*)(qmax_s + 1);             // 64
    int* a_best = a_cur + 64;                     // 64
    int* flag   = a_best + 64;                    // 1
    int* ef_s   = flag + 1;                       // 512
    int* et_s   = ef_s + EE;                      // 512

    const int tid    = threadIdx.x;
    const int b      = blockIdx.x;
    const int halfid = tid >> 4;        // 0..63 half-warp id
    const int hl     = tid & 15;        // lane within half-warp
    const int sseg   = hl & 3;          // column segment s (cols 4s..4s+3)
    const int kgrp   = hl >> 2;         // row-group k (rows 4i+k)
    const unsigned hmask = 0xFFFFu << ((halfid & 1) * 16);
    const int warp = tid >> 5;
    const int lane = tid & 31;
    // reduce-scatter final index permutation: perm[x] = [0,2,1,3][x]
    const int permS = ((sseg & 1) << 1) | (sseg >> 1);
    const int permK = ((kgrp & 1) << 1) | (kgrp >> 1);

    const float* nb    = nodev + (size_t)b * NN * AA;
    const float* ebase = edgev + (size_t)b * EE * AA * AA;

    // ---- init
    for (int i = tid; i < NN * AA; i += TPB) {
        float v = nb[i] * 0.015625f;   // /64 exact
        q0[i] = v; q[i] = v;
    }
    for (int i = tid; i < EE * AA; i += TPB) { mf[i] = 0.f; mb[i] = 0.f; }
    if (tid < EE) { ef_s[tid] = ef[tid]; et_s[tid] = et[tid]; }
    __syncthreads();

    // ---- argmax of q-array per node (lowest index wins ties, like jnp.argmax)
    // 64 half-warps -> node n = halfid, one each.
    auto do_argmax = [&](const float* qa) {
        const int n = halfid;
        float bv = qa[n * AA + hl]; int bi = hl;
        #pragma unroll
        for (int o = 8; o; o >>= 1) {
            float ov = __shfl_xor_sync(hmask, bv, o, 16);
            int   oi = __shfl_xor_sync(hmask, bi, o, 16);
            if (ov > bv || (ov == bv && oi < bi)) { bv = ov; bi = oi; }
        }
        if (hl == 0) a_cur[n] = bi;
    };

    // ---- evaluate action a_cur, update (q_max, a_best). Caller syncs before.
    // Edge term on warps 0..15 (whole warps -> full-warp shuffles safe);
    // reduction association identical to the proven 512-thread version.
    auto do_eval = [&](bool first) {
        if (tid < EE) {
            float ev;
            {
                int e  = tid;
                int af = a_cur[ef_s[e]];
                int at = a_cur[et_s[e]];
                ev = ebase[(size_t)e * 256 + af * 16 + at];
            }
            #pragma unroll
            for (int o = 16; o; o >>= 1) ev += __shfl_xor_sync(0xffffffffu, ev, o, 32);
            if (lane == 0) red[warp] = ev;
        }
        if (tid < NN) {
            float nv = q0[tid * AA + a_cur[tid]] * 64.0f;   // node_vals exact
            #pragma unroll
            for (int o = 16; o; o >>= 1) nv += __shfl_xor_sync(0xffffffffu, nv, o, 32);
            if (lane == 0) red_node[warp] = nv;
        }
        __syncthreads();
        if (tid == 0) {
            float es = 0.f;
            #pragma unroll
            for (int w = 0; w < 16; w++) es += red[w];
            float ns = red_node[0] + red_node[1];
            float qv = ns * (1.0f / 64.0f) + es * (1.0f / 512.0f);
            if (first || qv > *qmax_s) { *qmax_s = qv; *flag = 1; }
            else *flag = 0;
        }
        __syncthreads();
        if (*flag && tid < NN) a_best[tid] = a_cur[tid];
        __syncthreads();
    };

    // ---- initial: a_max = argmax(node_vals), q_max = eval
    do_argmax(q0);
    __syncthreads();
    do_eval(true);

    // ---- message-passing iterations
    for (int it = 0; it < ITERS; it++) {
        // Phase 1: one edge per half-warp per pass (8 passes over 64 hws).
        // Per-edge computation is instruction-for-instruction the proven R12
        // sequence: coalesced chunk-ownership loads, exact fmax reduce-
        // scatters, mean butterflies with the pinned association trees.
        for (int pass = 0; pass < 8; ++pass) {
            const int e = halfid + NHW * pass;
            const int nf = ef_s[e], nt = et_s[e];

            // ---- hoisted loads of ALL old state (before any store this pass)
            const float4 qnt4 = *(const float4*)(q  + nt * AA + 4 * sseg);
            const float4 mfo4 = *(const float4*)(mf + e  * AA + 4 * sseg);
            const float4 ubv  = f4_sub(qnt4, mfo4);      // ub[4s..4s+3]
            const float uf0 = q[nf * AA + 0  + kgrp] - mb[e * AA + 0  + kgrp];
            const float uf1 = q[nf * AA + 4  + kgrp] - mb[e * AA + 4  + kgrp];
            const float uf2 = q[nf * AA + 8  + kgrp] - mb[e * AA + 8  + kgrp];
            const float uf3 = q[nf * AA + 12 + kgrp] - mb[e * AA + 12 + kgrp];

            // ---- coalesced tile load
            const float4* g4 = (const float4*)(ebase + (size_t)e * 256);
            const float4 T0 = g4[ 0 + hl];
            const float4 T1 = g4[16 + hl];
            const float4 T2 = g4[32 + hl];
            const float4 T3 = g4[48 + hl];

            // ---- mb partials: p_i = row (4i+kgrp) max over own 4-col segment
            float p0 = seg_max(T0, ubv);
            float p1 = seg_max(T1, ubv);
            float p2 = seg_max(T2, ubv);
            float p3 = seg_max(T3, ubv);
            // reduce-scatter over s (xor 1 then 2); lane ends with row 4*permS+kgrp
            float mbv;
            {
                const bool s0 = (sseg & 1) != 0;
                float send0 = s0 ? p0 : p2, send1 = s0 ? p1 : p3;
                float keep0 = s0 ? p2 : p0, keep1 = s0 ? p3 : p1;
                float r0 = __shfl_xor_sync(hmask, send0, 1, 16);
                float r1 = __shfl_xor_sync(hmask, send1, 1, 16);
                float a0 = fmaxf(keep0, r0), a1 = fmaxf(keep1, r1);
                const bool s1 = (sseg & 2) != 0;
                float send = s1 ? a0 : a1, keep = s1 ? a1 : a0;
                float r = __shfl_xor_sync(hmask, send, 2, 16);
                mbv = fmaxf(keep, r);
            }

            // ---- mf candidates: C[j] = max over own rows, col 4s+j
            float cx = fmaxf(fmaxf(fmaf(T0.x, EINV, uf0), fmaf(T1.x, EINV, uf1)),
                             fmaxf(fmaf(T2.x, EINV, uf2), fmaf(T3.x, EINV, uf3)));
            float cy = fmaxf(fmaxf(fmaf(T0.y, EINV, uf0), fmaf(T1.y, EINV, uf1)),
                             fmaxf(fmaf(T2.y, EINV, uf2), fmaf(T3.y, EINV, uf3)));
            float cz = fmaxf(fmaxf(fmaf(T0.z, EINV, uf0), fmaf(T1.z, EINV, uf1)),
                             fmaxf(fmaf(T2.z, EINV, uf2), fmaf(T3.z, EINV, uf3)));
            float cw = fmaxf(fmaxf(fmaf(T0.w, EINV, uf0), fmaf(T1.w, EINV, uf1)),
                             fmaxf(fmaf(T2.w, EINV, uf2), fmaf(T3.w, EINV, uf3)));
            // reduce-scatter over k (xor 4 then 8); lane ends with col 4*sseg+permK
            float mfv;
            {
                const bool k0 = (kgrp & 1) != 0;
                float send0 = k0 ? cx : cz, send1 = k0 ? cy : cw;
                float keep0 = k0 ? cz : cx, keep1 = k0 ? cw : cy;
                float r0 = __shfl_xor_sync(hmask, send0, 4, 16);
                float r1 = __shfl_xor_sync(hmask, send1, 4, 16);
                float a0 = fmaxf(keep0, r0), a1 = fmaxf(keep1, r1);
                const bool k1 = (kgrp & 2) != 0;
                float send = k1 ? a0 : a1, keep = k1 ? a1 : a0;
                float r = __shfl_xor_sync(hmask, send, 8, 16);
                mfv = fmaxf(keep, r);
            }

            // ---- means with the pinned association trees.
            float smb = mbv;
            smb += __shfl_xor_sync(hmask, smb, 1, 16);
            smb += __shfl_xor_sync(hmask, smb, 2, 16);
            smb += __shfl_xor_sync(hmask, smb, 8, 16);
            smb += __shfl_xor_sync(hmask, smb, 4, 16);
            float smf = mfv;
            smf += __shfl_xor_sync(hmask, smf, 2, 16);
            smf += __shfl_xor_sync(hmask, smf, 1, 16);
            smf += __shfl_xor_sync(hmask, smf, 4, 16);
            smf += __shfl_xor_sync(hmask, smf, 8, 16);

            // ---- stores (bijective; butterflies ordered all lanes' old-state
            // loads before these writes)
            mb[e * AA + 4 * permS + kgrp] = mbv - smb * 0.0625f;
            mf[e * AA + 4 * sseg + permK] = mfv - smf * 0.0625f;
        }
        __syncthreads();

        // Phase 2: q = q0 + scatter(mf over edges_to) + scatter(mb over edges_from)
        // per node in ascending-edge order; node n = halfid (one per half-warp).
        {
            const int n = halfid;
            float acc = q0[n * AA + hl];
            int o0 = g_to_off[n], o1 = g_to_off[n + 1];
            for (int i = o0; i < o1; i++) acc += mf[g_to_lst[i] * AA + hl];
            o0 = g_from_off[n]; o1 = g_from_off[n + 1];
            for (int i = o0; i < o1; i++) acc += mb[g_from_lst[i] * AA + hl];
            q[n * AA + hl] = acc;
            float bv = acc; int bi = hl;
            #pragma unroll
            for (int o = 8; o; o >>= 1) {
                float ov = __shfl_xor_sync(hmask, bv, o, 16);
                int   oi = __shfl_xor_sync(hmask, bi, o, 16);
                if (ov > bv || (ov == bv && oi < bi)) { bv = ov; bi = oi; }
            }
            if (hl == 0) a_cur[n] = bi;
        }
        __syncthreads();

        // Phase 3: evaluate greedy action, keep best
        do_eval(false);
    }

    // ---- output: concat(q_max[B], float(a_max[B,N]))
    if (tid == 0) out[b] = *qmax_s;
    if (tid < NN) out[BB + (size_t)b * NN + tid] = (float)a_best[tid];
}

extern "C" void kernel_launch(void* const* d_in, const int* in_sizes, int n_in,
                              void* d_out, int out_size)
{
    const float* nodev = (const float*)d_in[0];   // (B,N,A) f32
    const float* edgev = (const float*)d_in[1];   // (B,E,A,A) f32
    const int*   ef    = (const int*)d_in[2];     // (E,) i32
    const int*   et    = (const int*)d_in[3];     // (E,) i32
    float* out = (float*)d_out;

    static bool attr_set = false;
    if (!attr_set) {
        cudaFuncSetAttribute(dcg_kernel, cudaFuncAttributeMaxDynamicSharedMemorySize, SMEM_BYTES);
        attr_set = true;
    }

    build_adj_kernel<<<1, 64>>>(ef, et);
    dcg_kernel<<<BB, TPB, SMEM_BYTES>>>(nodev, edgev, ef, et, out);
}

// round 15
// speedup vs baseline: 1.2781x; 1.1402x over previous
#include <cuda_runtime.h>
#include <math.h>
#include <stdint.h>

// Problem constants
#define BB 512
#define NN 64
#define EE 512
#define AA 16
#define ITERS 8
#define TPB 1024         // one fat CTA per batch; occ 1 (L2-resident tiles)
#define NHW (TPB / 16)   // 64 half-warps
#define EINV (1.0f / 512.0f)

// Adjacency (CSR, ascending edge order) -- built once per launch on device.
__device__ int g_to_off[NN + 1], g_from_off[NN + 1];
__device__ int g_to_lst[EE], g_from_lst[EE];

__global__ void build_adj_kernel(const int* __restrict__ ef, const int* __restrict__ et) {
    __shared__ int sf[EE], st[EE];
    __shared__ int cto[NN], cfr[NN];
    int t = threadIdx.x;
    for (int e = t; e < EE; e += blockDim.x) { sf[e] = ef[e]; st[e] = et[e]; }
    __syncthreads();
    if (t < NN) {
        int ct = 0, cf = 0;
        for (int e = 0; e < EE; e++) { ct += (st[e] == t); cf += (sf[e] == t); }
        cto[t] = ct; cfr[t] = cf;
    }
    __syncthreads();
    if (t == 0) {
        int a = 0, b = 0;
        for (int n = 0; n < NN; n++) {
            g_to_off[n] = a; a += cto[n];
            g_from_off[n] = b; b += cfr[n];
        }
        g_to_off[NN] = a; g_from_off[NN] = b;
    }
    __syncthreads();
    if (t < NN) {
        int ot = g_to_off[t], of = g_from_off[t];
        for (int e = 0; e < EE; e++) {
            if (st[e] == t) g_to_lst[ot++] = e;
            if (sf[e] == t) g_from_lst[of++] = e;
        }
    }
}

// SMEM words: q0 1024 + q 1024 + qT 1024 + mf 8192 + mbT 8192 + red 16 +
// red_node 2 + qmax 1 + a_cur 64 + a_best 64 + flag 1 + ef 512 + et 512 +
// to_off 65 + from_off 65 + to_lst 512 + from_lst 512  ~= 21.8K words ~= 87KB
// pad to 120KB: guarantees 1 CTA/SM so 148 resident CTAs' tiles (76MB) stay in L2.
#define SMEM_BYTES (120 * 1024)

__device__ __forceinline__ float4 f4_sub(float4 a, float4 b) {
    float4 r;
    r.x = a.x - b.x; r.y = a.y - b.y; r.z = a.z - b.z; r.w = a.w - b.w;
    return r;
}
// max over 4 elements of (T*EINV + u[j])  -- exact: T*EINV product exact,
// single rounding per add, fmax exactly associative.
__device__ __forceinline__ float seg_max(float4 T, float4 u) {
    float a = fmaxf(fmaf(T.x, EINV, u.x), fmaf(T.y, EINV, u.y));
    float b = fmaxf(fmaf(T.z, EINV, u.z), fmaf(T.w, EINV, u.w));
    return fmaxf(a, b);
}

__global__ __launch_bounds__(TPB, 1)
void dcg_kernel(const float* __restrict__ nodev, const float* __restrict__ edgev,
                const int* __restrict__ ef, const int* __restrict__ et,
                float* __restrict__ out)
{
    extern __shared__ float smem[];
    float* q0      = smem;                        // 1024
    float* q       = q0 + 1024;                   // 1024 (normal layout)
    float* qT      = q + 1024;                    // 1024 (transposed: [n][4k+i]=q[n][4i+k])
    float* mf      = qT + 1024;                   // 8192 (normal layout)
    float* mbT     = mf + 8192;                   // 8192 (transposed)
    float* red     = mbT + 8192;                  // 16
    float* red_node = red + 16;                   // 2
    float* qmax_s  = red_node + 2;                // 1
    int* a_cur   = (int*)(qmax_s + 1);            // 64
    int* a_best  = a_cur + 64;                    // 64
    int* flag    = a_best + 64;                   // 1
    int* ef_s    = flag + 1;                      // 512
    int* et_s    = ef_s + EE;                     // 512
    int* to_off  = et_s + EE;                     // 65
    int* from_off = to_off + (NN + 1);            // 65
    int* to_lst  = from_off + (NN + 1);           // 512
    int* from_lst = to_lst + EE;                  // 512

    const int tid    = threadIdx.x;
    const int b      = blockIdx.x;
    const int halfid = tid >> 4;        // 0..63 half-warp id
    const int hl     = tid & 15;        // lane within half-warp
    const int sseg   = hl & 3;          // column segment s (cols 4s..4s+3)
    const int kgrp   = hl >> 2;         // row-group k (rows 4i+k)
    const unsigned hmask = 0xFFFFu << ((halfid & 1) * 16);
    const int warp = tid >> 5;
    const int lane = tid & 31;
    // reduce-scatter final index permutation: perm[x] = [0,2,1,3][x]
    const int permS = ((sseg & 1) << 1) | (sseg >> 1);
    const int permK = ((kgrp & 1) << 1) | (kgrp >> 1);
    // transposed position of logical index hl
    const int tpos = 4 * (hl & 3) + (hl >> 2);

    const float* nb    = nodev + (size_t)b * NN * AA;
    const float* ebase = edgev + (size_t)b * EE * AA * AA;

    // ---- init
    {
        // one element per thread (TPB == NN*AA)
        int i = tid, n16 = i & ~15, a = i & 15;
        float v = nb[i] * 0.015625f;   // /64 exact
        q0[i] = v; q[i] = v;
        qT[n16 + 4 * (a & 3) + (a >> 2)] = v;
    }
    for (int i = tid; i < EE * AA; i += TPB) { mf[i] = 0.f; mbT[i] = 0.f; }
    if (tid < EE) {
        ef_s[tid] = ef[tid]; et_s[tid] = et[tid];
        to_lst[tid] = g_to_lst[tid]; from_lst[tid] = g_from_lst[tid];
    }
    if (tid >= EE && tid < EE + NN + 1) {
        int i = tid - EE;
        to_off[i] = g_to_off[i]; from_off[i] = g_from_off[i];
    }
    __syncthreads();

    // ---- initial greedy action: argmax of q0 per node (lowest index ties)
    {
        const int n = halfid;
        float bv = q0[n * AA + hl]; int bi = hl;
        #pragma unroll
        for (int o = 8; o; o >>= 1) {
            float ov = __shfl_xor_sync(hmask, bv, o, 16);
            int   oi = __shfl_xor_sync(hmask, bi, o, 16);
            if (ov > bv || (ov == bv && oi < bi)) { bv = ov; bi = oi; }
        }
        if (hl == 0) a_cur[n] = bi;
    }
    __syncthreads();

    int snap = 0;   // snapshot of a_cur[tid] for the in-flight eval (tid<64)

    // ---- phase 1 body (proven R12 instruction sequence; uf via transposed
    // mirrors). Returns nothing; writes mf/mbT for all 512 edges.
    auto phase1 = [&]() {
        for (int pass = 0; pass < 8; ++pass) {
            const int e = halfid + NHW * pass;
            const int nf = ef_s[e], nt = et_s[e];

            // hoisted old-state loads (before any store this pass)
            const float4 qnt4 = *(const float4*)(q  + nt * AA + 4 * sseg);
            const float4 mfo4 = *(const float4*)(mf + e  * AA + 4 * sseg);
            const float4 ubv  = f4_sub(qnt4, mfo4);      // ub[4s..4s+3]
            const float4 ufq  = *(const float4*)(qT  + nf * AA + 4 * kgrp);
            const float4 ufm  = *(const float4*)(mbT + e  * AA + 4 * kgrp);
            const float uf0 = ufq.x - ufm.x;   // q[nf][0+k]-mb[e][0+k]
            const float uf1 = ufq.y - ufm.y;   // q[nf][4+k]-mb[e][4+k]
            const float uf2 = ufq.z - ufm.z;   // q[nf][8+k]-mb[e][8+k]
            const float uf3 = ufq.w - ufm.w;   // q[nf][12+k]-mb[e][12+k]

            // coalesced tile load
            const float4* g4 = (const float4*)(ebase + (size_t)e * 256);
            const float4 T0 = g4[ 0 + hl];
            const float4 T1 = g4[16 + hl];
            const float4 T2 = g4[32 + hl];
            const float4 T3 = g4[48 + hl];

            // mb partials: p_i = row (4i+kgrp) max over own 4-col segment
            float p0 = seg_max(T0, ubv);
            float p1 = seg_max(T1, ubv);
            float p2 = seg_max(T2, ubv);
            float p3 = seg_max(T3, ubv);
            // reduce-scatter over s (xor 1 then 2); ends with row 4*permS+kgrp
            float mbv;
            {
                const bool s0 = (sseg & 1) != 0;
                float send0 = s0 ? p0 : p2, send1 = s0 ? p1 : p3;
                float keep0 = s0 ? p2 : p0, keep1 = s0 ? p3 : p1;
                float r0 = __shfl_xor_sync(hmask, send0, 1, 16);
                float r1 = __shfl_xor_sync(hmask, send1, 1, 16);
                float a0 = fmaxf(keep0, r0), a1 = fmaxf(keep1, r1);
                const bool s1 = (sseg & 2) != 0;
                float send = s1 ? a0 : a1, keep = s1 ? a1 : a0;
                float r = __shfl_xor_sync(hmask, send, 2, 16);
                mbv = fmaxf(keep, r);
            }

            // mf candidates: C[j] = max over own rows, col 4s+j
            float cx = fmaxf(fmaxf(fmaf(T0.x, EINV, uf0), fmaf(T1.x, EINV, uf1)),
                             fmaxf(fmaf(T2.x, EINV, uf2), fmaf(T3.x, EINV, uf3)));
            float cy = fmaxf(fmaxf(fmaf(T0.y, EINV, uf0), fmaf(T1.y, EINV, uf1)),
                             fmaxf(fmaf(T2.y, EINV, uf2), fmaf(T3.y, EINV, uf3)));
            float cz = fmaxf(fmaxf(fmaf(T0.z, EINV, uf0), fmaf(T1.z, EINV, uf1)),
                             fmaxf(fmaf(T2.z, EINV, uf2), fmaf(T3.z, EINV, uf3)));
            float cw = fmaxf(fmaxf(fmaf(T0.w, EINV, uf0), fmaf(T1.w, EINV, uf1)),
                             fmaxf(fmaf(T2.w, EINV, uf2), fmaf(T3.w, EINV, uf3)));
            // reduce-scatter over k (xor 4 then 8); ends with col 4*sseg+permK
            float mfv;
            {
                const bool k0 = (kgrp & 1) != 0;
                float send0 = k0 ? cx : cz, send1 = k0 ? cy : cw;
                float keep0 = k0 ? cz : cx, keep1 = k0 ? cw : cy;
                float r0 = __shfl_xor_sync(hmask, send0, 4, 16);
                float r1 = __shfl_xor_sync(hmask, send1, 4, 16);
                float a0 = fmaxf(keep0, r0), a1 = fmaxf(keep1, r1);
                const bool k1 = (kgrp & 2) != 0;
                float send = k1 ? a0 : a1, keep = k1 ? a1 : a0;
                float r = __shfl_xor_sync(hmask, send, 8, 16);
                mfv = fmaxf(keep, r);
            }

            // means with the pinned association trees
            float smb = mbv;
            smb += __shfl_xor_sync(hmask, smb, 1, 16);
            smb += __shfl_xor_sync(hmask, smb, 2, 16);
            smb += __shfl_xor_sync(hmask, smb, 8, 16);
            smb += __shfl_xor_sync(hmask, smb, 4, 16);
            float smf = mfv;
            smf += __shfl_xor_sync(hmask, smf, 2, 16);
            smf += __shfl_xor_sync(hmask, smf, 1, 16);
            smf += __shfl_xor_sync(hmask, smf, 4, 16);
            smf += __shfl_xor_sync(hmask, smf, 8, 16);

            // stores: logical mb row 4*permS+kgrp -> mbT pos 4*kgrp+permS;
            // mf col 4*sseg+permK in normal layout. Butterflies ordered all
            // lanes' old-state loads before these writes.
            mbT[e * AA + 4 * kgrp + permS] = mbv - smb * 0.0625f;
            mf [e * AA + 4 * sseg + permK] = mfv - smf * 0.0625f;
        }
    };

    // ================= main loop: 3 barrier regions per iteration =========
    for (int it = 0; it < ITERS; it++) {
        // -- R1: issue eval-gather loads for the CURRENT a_cur, then phase 1
        //        (independent: eval reads a_cur/raw inputs; phase1 writes
        //        mf/mbT only). LDG latency hides under phase-1 compute.
        float ev = 0.f, nv = 0.f;
        if (tid < EE) {
            int e  = tid;
            int af = a_cur[ef_s[e]];
            int at = a_cur[et_s[e]];
            ev = ebase[(size_t)e * 256 + af * 16 + at];
        }
        if (tid < NN) {
            snap = a_cur[tid];
            nv = q0[tid * AA + snap] * 64.0f;   // node_vals exact
        }

        phase1();

        // eval reductions (identical association to the proven sequence)
        if (tid < EE) {
            #pragma unroll
            for (int o = 16; o; o >>= 1) ev += __shfl_xor_sync(0xffffffffu, ev, o, 32);
            if (lane == 0) red[warp] = ev;
        }
        if (tid < NN) {
            #pragma unroll
            for (int o = 16; o; o >>= 1) nv += __shfl_xor_sync(0xffffffffu, nv, o, 32);
            if (lane == 0) red_node[warp] = nv;
        }
        __syncthreads();

        // -- R2: serial finalize
        if (tid == 0) {
            float es = 0.f;
            #pragma unroll
            for (int w = 0; w < 16; w++) es += red[w];
            float ns = red_node[0] + red_node[1];
            float qv = ns * (1.0f / 64.0f) + es * (1.0f / 512.0f);
            if (it == 0 || qv > *qmax_s) { *qmax_s = qv; *flag = 1; }
            else *flag = 0;
        }
        __syncthreads();

        // -- R3: a_best update (from snapshot) + phase 2 (q, qT, argmax)
        if (*flag && tid < NN) a_best[tid] = snap;
        {
            const int n = halfid;
            float acc = q0[n * AA + hl];
            int o0 = to_off[n], o1 = to_off[n + 1];
            for (int i = o0; i < o1; i++) acc += mf[to_lst[i] * AA + hl];
            o0 = from_off[n]; o1 = from_off[n + 1];
            for (int i = o0; i < o1; i++) acc += mbT[from_lst[i] * AA + tpos];
            q[n * AA + hl] = acc;
            qT[n * AA + tpos] = acc;
            float bv = acc; int bi = hl;
            #pragma unroll
            for (int o = 8; o; o >>= 1) {
                float ov = __shfl_xor_sync(hmask, bv, o, 16);
                int   oi = __shfl_xor_sync(hmask, bi, o, 16);
                if (ov > bv || (ov == bv && oi < bi)) { bv = ov; bi = oi; }
            }
            if (hl == 0) a_cur[n] = bi;
        }
        __syncthreads();
    }

    // ---- tail: evaluate the final iteration's greedy action
    {
        float ev = 0.f, nv = 0.f;
        if (tid < EE) {
            int e  = tid;
            int af = a_cur[ef_s[e]];
            int at = a_cur[et_s[e]];
            ev = ebase[(size_t)e * 256 + af * 16 + at];
            #pragma unroll
            for (int o = 16; o; o >>= 1) ev += __shfl_xor_sync(0xffffffffu, ev, o, 32);
            if (lane == 0) red[warp] = ev;
        }
        if (tid < NN) {
            snap = a_cur[tid];
            nv = q0[tid * AA + snap] * 64.0f;
            #pragma unroll
            for (int o = 16; o; o >>= 1) nv += __shfl_xor_sync(0xffffffffu, nv, o, 32);
            if (lane == 0) red_node[warp] = nv;
        }
        __syncthreads();
        if (tid == 0) {
            float es = 0.f;
            #pragma unroll
            for (int w = 0; w < 16; w++) es += red[w];
            float ns = red_node[0] + red_node[1];
            float qv = ns * (1.0f / 64.0f) + es * (1.0f / 512.0f);
            if (qv > *qmax_s) { *qmax_s = qv; *flag = 1; }
            else *flag = 0;
        }
        __syncthreads();
        if (*flag && tid < NN) a_best[tid] = snap;
        __syncthreads();
    }

    // ---- output: concat(q_max[B], float(a_max[B,N]))
    if (tid == 0) out[b] = *qmax_s;
    if (tid < NN) out[BB + (size_t)b * NN + tid] = (float)a_best[tid];
}

extern "C" void kernel_launch(void* const* d_in, const int* in_sizes, int n_in,
                              void* d_out, int out_size)
{
    const float* nodev = (const float*)d_in[0];   // (B,N,A) f32
    const float* edgev = (const float*)d_in[1];   // (B,E,A,A) f32
    const int*   ef    = (const int*)d_in[2];     // (E,) i32
    const int*   et    = (const int*)d_in[3];     // (E,) i32
    float* out = (float*)d_out;

    static bool attr_set = false;
    if (!attr_set) {
        cudaFuncSetAttribute(dcg_kernel, cudaFuncAttributeMaxDynamicSharedMemorySize, SMEM_BYTES);
        attr_set = true;
    }

    build_adj_kernel<<<1, 64>>>(ef, et);
    dcg_kernel<<<BB, TPB, SMEM_BYTES>>>(nodev, edgev, ef, et, out);
}